// round 7
// baseline (speedup 1.0000x reference)
#include <cuda_runtime.h>
#include <math.h>
#include <stdint.h>

// FineMatchingModule — algebraically collapsed (verified R3-R6, rel_err ~1.5e-8):
// attention layers add only window-uniform shifts which the final softmax
// cancels. Per point:
//   corr[n] = sum_j s[j] * flat[n*256+j],  n = 0..24
// flat = channel-major-flattened zero-padded 5x5 window of target_features at
// the truncated coarse position; s = center pixel channel vector (= pixel 12).
// refined = pos + softmax(corr) @ offsets, offsets1d = linspace(-3,2,5).
//
// R7: persistent CTAs (304 = 2/SM) with a cp.async double-buffered pipeline.
// Each iteration: issue NEXT pair's full 51.2KB window fetch (cp.async.cg,
// gmem->smem, no registers), wait current pair's group, compute from smem.
// DRAM fetch of pair i+1 fully overlaps compute of pair i -> continuous HBM
// stream. No atomics / no shuffles in the reduction (static token gather).

#define B_ 4
#define K_ 1024
#define H_ 256
#define W_ 256
#define C_ 256
#define NPAIR 2048            // B*K / 2
#define GRID_ 304             // 152 SMs x 2 resident CTAs

// smem (floats): tile[2 buf][2 pt][25*256]  + pa[2][128] + pb[2][128]
#define TILE_F   6400         // floats per point tile
#define PAIR_F   (2 * TILE_F) // 12800
#define PA_OFF   (2 * PAIR_F) // 25600
#define PB_OFF   (PA_OFF + 256)
#define SMEM_F   (PB_OFF + 256)          // 26112 floats
#define SMEM_B   (SMEM_F * 4)            // 104448 bytes

__device__ __forceinline__ void prefetch_pair(const float* __restrict__ tf,
                                              const float* __restrict__ pos,
                                              float* __restrict__ tile,  // [2][TILE_F]
                                              int pair, int tid)
{
    #pragma unroll
    for (int h = 0; h < 2; ++h) {
        const int pt = 2 * pair + h;
        const int b  = pt >> 10;                       // K = 1024
        const int r  = (int)__ldg(&pos[2 * pt + 0]);   // pos >= 0 -> trunc ok
        const int c  = (int)__ldg(&pos[2 * pt + 1]);
        const float* fb = tf + (size_t)b * (H_ * W_ * C_);
        float* dstb = tile + h * TILE_F;

        // 25 pixels x 1KB, in 16B chunks: 1600 chunk-ops over 256 threads.
        for (int idx = tid; idx < 1600; idx += 256) {
            const int p = idx >> 6;            // pixel 0..24
            const int o = (idx & 63) << 2;     // float offset within pixel
            const int rr = r - 2 + p / 5;
            const int cc = c - 2 + p % 5;
            float* dst = dstb + p * 256 + o;
            if (rr >= 0 && rr < H_ && cc >= 0 && cc < W_) {
                const float* src = fb + ((size_t)rr * W_ + cc) * C_ + o;
                const uint32_t ds = (uint32_t)__cvta_generic_to_shared(dst);
                asm volatile("cp.async.cg.shared.global [%0], [%1], 16;\n"
                             :: "r"(ds), "l"(src));
            } else {
                *(float4*)dst = make_float4(0.f, 0.f, 0.f, 0.f);  // zero-pad
            }
        }
    }
    asm volatile("cp.async.commit_group;\n" ::: "memory");
}

__global__ __launch_bounds__(256)
void fine_match_kernel(const float* __restrict__ tf,
                       const float* __restrict__ pos,
                       float* __restrict__ out)
{
    extern __shared__ float sm[];
    float* pa = sm + PA_OFF;   // [2][128]
    float* pb = sm + PB_OFF;   // [2][128]

    const int tid  = threadIdx.x;
    const int half = tid >> 7;           // point slot in pair
    const int q    = tid & 127;          // owns channels 2q, 2q+1

    int i  = blockIdx.x;
    if (i >= NPAIR) return;

    prefetch_pair(tf, pos, sm, i, tid);  // prologue: pair i -> buffer 0

    for (int it = 0; i < NPAIR; i += GRID_, ++it) {
        const int cur = it & 1;
        const bool hasnext = (i + GRID_) < NPAIR;
        if (hasnext)
            prefetch_pair(tf, pos, sm + (cur ^ 1) * PAIR_F, i + GRID_, tid);

        // own point's position (tiny, L2-resident)
        const int pt = 2 * i + half;
        const float pr = pos[2 * pt + 0];
        const float pc = pos[2 * pt + 1];

        if (hasnext) asm volatile("cp.async.wait_group 1;\n" ::: "memory");
        else         asm volatile("cp.async.wait_group 0;\n" ::: "memory");
        __syncthreads();                                   // tile[cur] ready

        // ---- products: idx = 50q + i2, i2 = p (ch 2q) / 25+p (ch 2q+1).
        // Token n = idx>>8; one 256-boundary max -> two accumulators.
        const float* tb = sm + cur * PAIR_F + half * TILE_F;
        const int sb    = (50 * q) & 255;
        const int split = 256 - sb;
        float a0 = 0.0f, a1 = 0.0f;
        #pragma unroll
        for (int p = 0; p < 25; ++p) {
            const float2 v = *(const float2*)(tb + p * 256 + 2 * q);
            const float s0 = tb[12 * 256 + ((sb + p) & 255)];
            const float s1 = tb[12 * 256 + ((sb + 25 + p) & 255)];
            const float t0 = v.x * s0;
            const float t1 = v.y * s1;
            if (p < split)      a0 += t0; else a1 += t0;
            if (p + 25 < split) a0 += t1; else a1 += t1;
        }
        pa[half * 128 + q] = a0;         // plain STS — no atomics
        pb[half * 128 + q] = a1;
        __syncthreads();                 // partials ready; tile[cur] free

        // ---- one warp per point: static gather + softmax + write ----
        if ((tid & 127) < 32) {
            const int lane = tid & 31;
            float logit = -INFINITY;
            if (lane < 25) {
                const int n  = lane;
                const int t0 = (256 * n + 49) / 50;
                const int t1 = (256 * n + 255) / 50;
                float ssv = (n > 0) ? pb[half * 128 + t0 - 1] : 0.0f;
                #pragma unroll 6
                for (int t = t0; t <= t1; ++t) ssv += pa[half * 128 + t];
                logit = ssv;
            }
            float m = logit;
            #pragma unroll
            for (int o = 16; o > 0; o >>= 1)
                m = fmaxf(m, __shfl_xor_sync(0xffffffffu, m, o));
            float e = (lane < 25) ? expf(logit - m) : 0.0f;
            float se = e;
            #pragma unroll
            for (int o = 16; o > 0; o >>= 1)
                se += __shfl_xor_sync(0xffffffffu, se, o);
            const float prb = e / se;    // 0 for lane >= 25

            // offsets: linspace(-3,2,5) = -3 + 1.25*k (exact fp32)
            const int ir = lane / 5;
            const int ic = lane - ir * 5;
            float dr = prb * (-3.0f + 1.25f * (float)ir);
            float dc = prb * (-3.0f + 1.25f * (float)ic);
            #pragma unroll
            for (int o = 16; o > 0; o >>= 1) {
                dr += __shfl_xor_sync(0xffffffffu, dr, o);
                dc += __shfl_xor_sync(0xffffffffu, dc, o);
            }
            if (lane == 0) {
                out[2 * pt + 0] = pr + dr;
                out[2 * pt + 1] = pc + dc;
            }
        }
        // next iteration's prefetch reuses tile[cur] — all reads done (sync#2)
    }
}

extern "C" void kernel_launch(void* const* d_in, const int* in_sizes, int n_in,
                              void* d_out, int out_size)
{
    (void)in_sizes; (void)n_in; (void)out_size;
    // metadata order: 0=source_features (unused by reference), 1=target_features,
    // 2=coarse_positions, 3..6 = Wq,Wk,Wv,Wo (cancel algebraically)
    const float* tf  = (const float*)d_in[1];
    const float* pos = (const float*)d_in[2];
    float* out = (float*)d_out;

    cudaFuncSetAttribute(fine_match_kernel,
                         cudaFuncAttributeMaxDynamicSharedMemorySize, SMEM_B);
    fine_match_kernel<<<GRID_, 256, SMEM_B>>>(tf, pos, out);
}

// round 8
// speedup vs baseline: 1.9796x; 1.9796x over previous
#include <cuda_runtime.h>
#include <math.h>

// FineMatchingModule — algebraically collapsed (verified R3-R7, rel_err ~1.5e-8):
// both attention layers add only window-uniform shifts which the final softmax
// cancels. Per point:
//   corr[n] = sum_j s[j] * flat[n*256+j],  n = 0..24
// flat = channel-major-flattened zero-padded 5x5 window of target_features at
// the truncated coarse position; s = center pixel channel vector (= pixel 12).
// refined = pos + softmax(corr) @ offsets, offsets1d = linspace(-3,2,5).
//
// R8: persistent CTAs (456 = 3/SM), register double-buffered pipeline.
// Product loop for pair k interleaves the 25 LDGs of pair k+1 into the same
// registers right after each v[p] is consumed -> DRAM demand is continuous
// (no load/compute phase lockstep). One barrier per pair; parity-buffered
// s / pa / pb; softmax on a rotating warp overlapped with next products.
// No atomics, no shuffles in the reduction (static token gather).

#define B_ 4
#define K_ 1024
#define H_ 256
#define W_ 256
#define C_ 256
#define NPAIR 2048            // B*K / 2
#define GRID_ 456             // 152 SMs x 3 resident CTAs

// product of pixel p for this thread's two channels (idx = 50q + p / 50q+25+p)
#define PROD(p) do {                                        \
    const float t0_ = v[p].x * s0[(p)];                     \
    const float t1_ = v[p].y * s0[25 + (p)];                \
    if ((p) < split)      a0 += t0_; else a1 += t0_;        \
    if ((p) + 25 < split) a0 += t1_; else a1 += t1_;        \
} while (0)

__global__ __launch_bounds__(256, 3)
void fine_match_kernel(const float* __restrict__ tf,
                       const float* __restrict__ pos,
                       float* __restrict__ out)
{
    // parity-buffered per-point state
    __shared__ float s_sh[2][2][312];    // center vector + 50-entry wrap
    __shared__ float pa[2][2][128];
    __shared__ float pb[2][2][128];

    const int tid  = threadIdx.x;
    const int half = tid >> 7;           // point slot within pair
    const int q    = tid & 127;          // owns channels 2q, 2q+1
    const int wrp  = tid >> 5;

    const int sb    = (50 * q) & 255;
    const int split = 256 - sb;

    int i = blockIdx.x;                  // pair index (grid-stride)
    if (i >= NPAIR) return;

    float2 v[25];
    float pr, pc;

    // ---- prolog: load pair i's window ----
    {
        const int pt = 2 * i + half;
        pr = pos[2 * pt + 0];
        pc = pos[2 * pt + 1];
        const int r = (int)pr, c = (int)pc;    // pos >= 0 -> trunc == astype
        const float* fb = tf + (size_t)(pt >> 10) * (H_ * W_ * C_);
        const bool interior = (r >= 2) & (r <= H_ - 3) & (c >= 2) & (c <= W_ - 3);
        if (interior) {
            const float2* nb =
                (const float2*)(fb + ((size_t)(r - 2) * W_ + (c - 2)) * C_) + q;
            #pragma unroll
            for (int p = 0; p < 25; ++p)
                v[p] = nb[(p / 5) * (W_ * (C_ / 2)) + (p % 5) * (C_ / 2)];
        } else {
            #pragma unroll
            for (int p = 0; p < 25; ++p) {
                const int rr = r - 2 + p / 5, cc = c - 2 + p % 5;
                v[p] = make_float2(0.f, 0.f);
                if (rr >= 0 && rr < H_ && cc >= 0 && cc < W_)
                    v[p] = ((const float2*)(fb + ((size_t)rr * W_ + cc) * C_))[q];
            }
        }
        s_sh[0][half][2 * q]     = v[12].x;
        s_sh[0][half][2 * q + 1] = v[12].y;
        if (q < 25) {
            s_sh[0][half][256 + 2 * q]     = v[12].x;
            s_sh[0][half][256 + 2 * q + 1] = v[12].y;
        }
    }
    __syncthreads();

    // ---- main pipelined loop ----
    for (int it = 0; i < NPAIR; i += GRID_, ++it) {
        const int  cur     = it & 1;
        const int  inext   = i + GRID_;
        const bool hasnext = inext < NPAIR;

        // next pair's position / base (independent L2 loads, overlap products)
        float npr = 0.f, npc = 0.f;
        const float* nfb = tf;
        int nr = 2, nc = 2;
        bool nint = true;
        if (hasnext) {
            const int npt = 2 * inext + half;
            npr = pos[2 * npt + 0];
            npc = pos[2 * npt + 1];
            nr = (int)npr; nc = (int)npc;
            nfb = tf + (size_t)(npt >> 10) * (H_ * W_ * C_);
            nint = (nr >= 2) & (nr <= H_ - 3) & (nc >= 2) & (nc <= W_ - 3);
        }

        const float* s0 = &s_sh[cur][half][sb];
        float a0 = 0.f, a1 = 0.f;

        if (hasnext & nint) {
            const float2* nb =
                (const float2*)(nfb + ((size_t)(nr - 2) * W_ + (nc - 2)) * C_) + q;
            #pragma unroll
            for (int p = 0; p < 25; ++p) {
                PROD(p);                                       // consume v[p]
                v[p] = nb[(p / 5) * (W_ * (C_ / 2)) + (p % 5) * (C_ / 2)];
            }
        } else if (hasnext) {
            #pragma unroll
            for (int p = 0; p < 25; ++p) {
                PROD(p);
                const int rr = nr - 2 + p / 5, cc = nc - 2 + p % 5;
                float2 nv = make_float2(0.f, 0.f);
                if (rr >= 0 && rr < H_ && cc >= 0 && cc < W_)
                    nv = ((const float2*)(nfb + ((size_t)rr * W_ + cc) * C_))[q];
                v[p] = nv;
            }
        } else {
            #pragma unroll
            for (int p = 0; p < 25; ++p) PROD(p);
        }

        pa[cur][half][q] = a0;          // plain STS — no atomics
        pb[cur][half][q] = a1;

        if (hasnext) {                  // stage next pair's s (its pixel 12)
            s_sh[cur ^ 1][half][2 * q]     = v[12].x;
            s_sh[cur ^ 1][half][2 * q + 1] = v[12].y;
            if (q < 25) {
                s_sh[cur ^ 1][half][256 + 2 * q]     = v[12].x;
                s_sh[cur ^ 1][half][256 + 2 * q + 1] = v[12].y;
            }
        }
        __syncthreads();                // one barrier per pair

        // ---- rotating warp per point: static gather + softmax + write ----
        if ((wrp & 3) == (it & 3)) {
            const int lane = tid & 31;
            float logit = -INFINITY;
            if (lane < 25) {
                const int n  = lane;
                const int t0 = (256 * n + 49) / 50;
                const int t1 = (256 * n + 255) / 50;
                float sum = (n > 0) ? pb[cur][half][t0 - 1] : 0.0f;
                #pragma unroll 6
                for (int t = t0; t <= t1; ++t) sum += pa[cur][half][t];
                logit = sum;
            }
            float m = logit;
            #pragma unroll
            for (int o = 16; o > 0; o >>= 1)
                m = fmaxf(m, __shfl_xor_sync(0xffffffffu, m, o));
            float e = (lane < 25) ? expf(logit - m) : 0.0f;
            float se = e;
            #pragma unroll
            for (int o = 16; o > 0; o >>= 1)
                se += __shfl_xor_sync(0xffffffffu, se, o);
            const float prb = e / se;   // 0 for lane >= 25

            // offsets: linspace(-3,2,5) = -3 + 1.25*k (exact fp32)
            const int ir = lane / 5;
            const int ic = lane - ir * 5;
            float dr = prb * (-3.0f + 1.25f * (float)ir);
            float dc = prb * (-3.0f + 1.25f * (float)ic);
            #pragma unroll
            for (int o = 16; o > 0; o >>= 1) {
                dr += __shfl_xor_sync(0xffffffffu, dr, o);
                dc += __shfl_xor_sync(0xffffffffu, dc, o);
            }
            if (lane == 0) {
                const int pt = 2 * i + half;
                out[2 * pt + 0] = pr + dr;
                out[2 * pt + 1] = pc + dc;
            }
        }

        pr = npr; pc = npc;             // roll position state
    }
}

extern "C" void kernel_launch(void* const* d_in, const int* in_sizes, int n_in,
                              void* d_out, int out_size)
{
    (void)in_sizes; (void)n_in; (void)out_size;
    // metadata order: 0=source_features (unused by reference), 1=target_features,
    // 2=coarse_positions, 3..6 = Wq,Wk,Wv,Wo (cancel algebraically)
    const float* tf  = (const float*)d_in[1];
    const float* pos = (const float*)d_in[2];
    float* out = (float*)d_out;

    fine_match_kernel<<<GRID_, 256>>>(tf, pos, out);
}

// round 10
// speedup vs baseline: 2.8955x; 1.4627x over previous
#include <cuda_runtime.h>
#include <math.h>

// FineMatchingModule — algebraically collapsed (verified R3-R8, rel_err ~1.5e-8):
// attention layers add only window-uniform shifts which the final softmax
// cancels. Per point:
//   corr[n] = sum_j s[j] * flat[n*256+j],  n = 0..24
// flat[25*ch + p] = channel-major-flattened zero-padded 5x5 window of
// target_features at the truncated coarse position; s = center pixel channel
// vector (= pixel 12). refined = pos + softmax(corr) @ offsets,
// offsets1d = linspace(-3,2,5).  (R9's "own-s" mapping was WRONG: token n
// mixes channels/pixels, so cross-channel s staging is mandatory.)
//
// R10: R6 math + streaming 8-deep register buffer (3 batches of 8 pixels,
// next batch's LDGs issued inside current batch's consume) -> window hold
// drops 50->16 regs, launch_bounds(256,5) -> ~60% occupancy, load issue is
// spread through compute. One staging barrier; dual-accumulator static-token
// reduction (no atomics / no reduction shuffles), per-point gather warp.

#define B_ 4
#define K_ 1024
#define H_ 256
#define W_ 256
#define C_ 256

// float2-unit offset of pixel p from window base pointer
#define OFFP(p) (((p) / 5) * (W_ * (C_ / 2)) + ((p) % 5) * (C_ / 2))

// products of pixel p for this thread's channels: idx = 50q + p (x), +25 (y)
#define PROD(p, vv) do {                                            \
    const float sx_ = s0[(p)];                                      \
    const float sy_ = s0[25 + (p)];                                 \
    if ((p) < split)      a0 = fmaf((vv).x, sx_, a0);               \
    else                  a1 = fmaf((vv).x, sx_, a1);               \
    if ((p) + 25 < split) a0 = fmaf((vv).y, sy_, a0);               \
    else                  a1 = fmaf((vv).y, sy_, a1);               \
} while (0)

__device__ __forceinline__ float2 ldwin(const float* __restrict__ fb,
                                        int r, int c, int p, int q)
{
    const int rr = r - 2 + p / 5, cc = c - 2 + p % 5;
    if (rr >= 0 && rr < H_ && cc >= 0 && cc < W_)
        return ((const float2*)(fb + ((size_t)rr * W_ + cc) * C_))[q];
    return make_float2(0.f, 0.f);
}

__global__ __launch_bounds__(256, 5)
void fine_match_kernel(const float* __restrict__ tf,
                       const float* __restrict__ pos,
                       float* __restrict__ out)
{
    __shared__ float s_sh[2][312];       // center vector + 50-entry wrap
    __shared__ float pa[2][128];
    __shared__ float pb[2][128];

    const int tid  = threadIdx.x;
    const int half = tid >> 7;           // point slot within CTA
    const int q    = tid & 127;          // owns channels 2q, 2q+1

    const int pt = (blockIdx.x << 1) | half;
    const float pr = pos[2 * pt + 0];
    const float pc = pos[2 * pt + 1];
    const int r = (int)pr, c = (int)pc;  // pos >= 0 -> trunc == astype(int32)
    const float* fb = tf + (size_t)(pt >> 10) * (H_ * W_ * C_);

    const int sb    = (50 * q) & 255;
    const int split = 256 - sb;          // product index >= split -> token n0+1

    // pixel order excluding center (12): three batches of 8
    const int P[24] = { 0, 1, 2, 3, 4, 5, 6, 7,
                        8, 9,10,11,13,14,15,16,
                       17,18,19,20,21,22,23,24 };

    float a0 = 0.f, a1 = 0.f;
    const float* s0;
    float2 v12;
    float2 buf[8];

    const bool interior = (r >= 2) & (r <= H_ - 3) & (c >= 2) & (c <= W_ - 3);
    if (interior) {
        const float2* base =
            (const float2*)(fb + ((size_t)(r - 2) * W_ + (c - 2)) * C_) + q;
        v12 = base[OFFP(12)];                      // s source first
        #pragma unroll
        for (int j = 0; j < 8; ++j) buf[j] = base[OFFP(P[j])];

        s_sh[half][2 * q]     = v12.x;             // stage s (+wrap)
        s_sh[half][2 * q + 1] = v12.y;
        if (q < 25) {
            s_sh[half][256 + 2 * q]     = v12.x;
            s_sh[half][256 + 2 * q + 1] = v12.y;
        }
        __syncthreads();
        s0 = &s_sh[half][sb];

        #pragma unroll                              // batch 0 -> load batch 1
        for (int j = 0; j < 8; ++j) {
            const float2 v = buf[j];
            buf[j] = base[OFFP(P[8 + j])];
            PROD(P[j], v);
        }
        #pragma unroll                              // batch 1 -> load batch 2
        for (int j = 0; j < 8; ++j) {
            const float2 v = buf[j];
            buf[j] = base[OFFP(P[16 + j])];
            PROD(P[8 + j], v);
        }
        PROD(12, v12);                              // center products
        #pragma unroll                              // batch 2
        for (int j = 0; j < 8; ++j) PROD(P[16 + j], buf[j]);
    } else {
        // border path (~3% of points, half-CTA uniform): same streaming shape
        v12 = ldwin(fb, r, c, 12, q);               // center always in-bounds
        #pragma unroll
        for (int j = 0; j < 8; ++j) buf[j] = ldwin(fb, r, c, P[j], q);

        s_sh[half][2 * q]     = v12.x;
        s_sh[half][2 * q + 1] = v12.y;
        if (q < 25) {
            s_sh[half][256 + 2 * q]     = v12.x;
            s_sh[half][256 + 2 * q + 1] = v12.y;
        }
        __syncthreads();
        s0 = &s_sh[half][sb];

        #pragma unroll
        for (int j = 0; j < 8; ++j) {
            const float2 v = buf[j];
            buf[j] = ldwin(fb, r, c, P[8 + j], q);
            PROD(P[j], v);
        }
        #pragma unroll
        for (int j = 0; j < 8; ++j) {
            const float2 v = buf[j];
            buf[j] = ldwin(fb, r, c, P[16 + j], q);
            PROD(P[8 + j], v);
        }
        PROD(12, v12);
        #pragma unroll
        for (int j = 0; j < 8; ++j) PROD(P[16 + j], buf[j]);
    }

    pa[half][q] = a0;                    // plain STS — no atomics
    pb[half][q] = a1;
    __syncthreads();

    // ---- one warp per point: static gather + softmax + expected offset ----
    if ((tid & 127) < 32) {              // warp 0 (point A), warp 4 (point B)
        const int lane = tid & 31;
        float logit = -INFINITY;
        if (lane < 25) {
            const int n  = lane;
            const int t0 = (256 * n + 49) / 50;    // first a0 contributor
            const int t1 = (256 * n + 255) / 50;   // last  a0 contributor
            float sum = (n > 0) ? pb[half][t0 - 1] : 0.0f;
            #pragma unroll 6
            for (int t = t0; t <= t1; ++t) sum += pa[half][t];  // 5-6 iters
            logit = sum;
        }
        float m = logit;
        #pragma unroll
        for (int o = 16; o > 0; o >>= 1)
            m = fmaxf(m, __shfl_xor_sync(0xffffffffu, m, o));
        float e = (lane < 25) ? expf(logit - m) : 0.0f;
        float se = e;
        #pragma unroll
        for (int o = 16; o > 0; o >>= 1)
            se += __shfl_xor_sync(0xffffffffu, se, o);
        const float prb = e / se;        // 0 for lane >= 25

        // offsets: linspace(-3, 2, 5) = -3 + 1.25*k (exact fp32)
        const int ir = lane / 5;
        const int ic = lane - ir * 5;
        float dr = prb * (-3.0f + 1.25f * (float)ir);
        float dc = prb * (-3.0f + 1.25f * (float)ic);
        #pragma unroll
        for (int o = 16; o > 0; o >>= 1) {
            dr += __shfl_xor_sync(0xffffffffu, dr, o);
            dc += __shfl_xor_sync(0xffffffffu, dc, o);
        }
        if (lane == 0) {
            out[2 * pt + 0] = pr + dr;
            out[2 * pt + 1] = pc + dc;
        }
    }
}

extern "C" void kernel_launch(void* const* d_in, const int* in_sizes, int n_in,
                              void* d_out, int out_size)
{
    (void)in_sizes; (void)n_in; (void)out_size;
    // metadata order: 0=source_features (unused by reference), 1=target_features,
    // 2=coarse_positions, 3..6 = Wq,Wk,Wv,Wo (cancel algebraically)
    const float* tf  = (const float*)d_in[1];
    const float* pos = (const float*)d_in[2];
    float* out = (float*)d_out;

    fine_match_kernel<<<(B_ * K_) / 2, 256>>>(tf, pos, out);
}

// round 11
// speedup vs baseline: 2.9450x; 1.0171x over previous
#include <cuda_runtime.h>
#include <math.h>

// FineMatchingModule — algebraically collapsed (verified R3-R10, rel_err ~1.5e-8):
// attention layers add only window-uniform shifts which the final softmax
// cancels. Per point:
//   corr[n] = sum_j s[j] * flat[n*256+j],  n = 0..24
// flat[25*ch + p] = channel-major-flattened zero-padded 5x5 window of
// target_features at the truncated coarse position; s = center pixel channel
// vector (= pixel 12). refined = pos + softmax(corr) @ offsets,
// offsets1d = linspace(-3,2,5).
//
// R11: finer grain. 128-thread CTA = ONE point; ~10 CTAs/SM -> 40 warps with
// 10 independent scheduling units (de-correlated phases, smooth DRAM demand),
// 4-warp barriers. Streaming 4-deep register buffer: 6 consume-batches, each
// issuing the next batch's 4 LDGs (load issue spread through compute, window
// hold = 8 regs). One staging barrier; dual-accumulator static-token
// reduction (no atomics / no reduction shuffles); warp-0 softmax.

#define B_ 4
#define K_ 1024
#define H_ 256
#define W_ 256
#define C_ 256

// float2-unit offset of pixel p from window base pointer
#define OFFP(p) (((p) / 5) * (W_ * (C_ / 2)) + ((p) % 5) * (C_ / 2))

// products of pixel p for this thread's channels: idx = 50q + p (x), +25 (y)
#define PROD(p, vv) do {                                            \
    const float sx_ = s0[(p)];                                      \
    const float sy_ = s0[25 + (p)];                                 \
    if ((p) < split)      a0 = fmaf((vv).x, sx_, a0);               \
    else                  a1 = fmaf((vv).x, sx_, a1);               \
    if ((p) + 25 < split) a0 = fmaf((vv).y, sy_, a0);               \
    else                  a1 = fmaf((vv).y, sy_, a1);               \
} while (0)

__device__ __forceinline__ float2 ldwin(const float* __restrict__ fb,
                                        int r, int c, int p, int q)
{
    const int rr = r - 2 + p / 5, cc = c - 2 + p % 5;
    if (rr >= 0 && rr < H_ && cc >= 0 && cc < W_)
        return ((const float2*)(fb + ((size_t)rr * W_ + cc) * C_))[q];
    return make_float2(0.f, 0.f);
}

__global__ __launch_bounds__(128, 10)
void fine_match_kernel(const float* __restrict__ tf,
                       const float* __restrict__ pos,
                       float* __restrict__ out)
{
    __shared__ float s_sh[312];          // center vector + 50-entry wrap
    __shared__ float pa[128];
    __shared__ float pb[128];

    const int q  = threadIdx.x;          // owns channels 2q, 2q+1
    const int pt = blockIdx.x;           // one point per CTA

    const float pr = pos[2 * pt + 0];
    const float pc = pos[2 * pt + 1];
    const int r = (int)pr, c = (int)pc;  // pos >= 0 -> trunc == astype(int32)
    const float* fb = tf + (size_t)(pt >> 10) * (H_ * W_ * C_);   // K = 1024

    const int sb    = (50 * q) & 255;
    const int split = 256 - sb;          // product index >= split -> token n0+1

    // pixel order excluding center (12): six batches of 4
    const int P[24] = { 0, 1, 2, 3,   4, 5, 6, 7,
                        8, 9,10,11,  13,14,15,16,
                       17,18,19,20,  21,22,23,24 };

    float a0 = 0.f, a1 = 0.f;
    const float* s0;
    float2 v12;
    float2 buf[4];

    const bool interior = (r >= 2) & (r <= H_ - 3) & (c >= 2) & (c <= W_ - 3);
    if (interior) {
        const float2* base =
            (const float2*)(fb + ((size_t)(r - 2) * W_ + (c - 2)) * C_) + q;
        v12 = base[OFFP(12)];                       // s source first
        #pragma unroll
        for (int j = 0; j < 4; ++j) buf[j] = base[OFFP(P[j])];

        s_sh[2 * q]     = v12.x;                    // stage s (+wrap)
        s_sh[2 * q + 1] = v12.y;
        if (q < 25) {
            s_sh[256 + 2 * q]     = v12.x;
            s_sh[256 + 2 * q + 1] = v12.y;
        }
        __syncthreads();
        s0 = &s_sh[sb];

        #pragma unroll
        for (int bt = 0; bt < 5; ++bt) {            // consume bt, load bt+1
            #pragma unroll
            for (int j = 0; j < 4; ++j) {
                const float2 v = buf[j];
                buf[j] = base[OFFP(P[4 * (bt + 1) + j])];
                PROD(P[4 * bt + j], v);
            }
        }
        PROD(12, v12);                              // center products
        #pragma unroll
        for (int j = 0; j < 4; ++j) PROD(P[20 + j], buf[j]);
    } else {
        // border path (~3% of points, CTA-uniform): same streaming shape
        v12 = ldwin(fb, r, c, 12, q);               // center always in-bounds
        #pragma unroll
        for (int j = 0; j < 4; ++j) buf[j] = ldwin(fb, r, c, P[j], q);

        s_sh[2 * q]     = v12.x;
        s_sh[2 * q + 1] = v12.y;
        if (q < 25) {
            s_sh[256 + 2 * q]     = v12.x;
            s_sh[256 + 2 * q + 1] = v12.y;
        }
        __syncthreads();
        s0 = &s_sh[sb];

        #pragma unroll
        for (int bt = 0; bt < 5; ++bt) {
            #pragma unroll
            for (int j = 0; j < 4; ++j) {
                const float2 v = buf[j];
                buf[j] = ldwin(fb, r, c, P[4 * (bt + 1) + j], q);
                PROD(P[4 * bt + j], v);
            }
        }
        PROD(12, v12);
        #pragma unroll
        for (int j = 0; j < 4; ++j) PROD(P[20 + j], buf[j]);
    }

    pa[q] = a0;                          // plain STS — no atomics
    pb[q] = a1;
    __syncthreads();

    // ---- warp 0: static gather + softmax + expected offset ----
    if (q < 32) {
        const int lane = q;
        float logit = -INFINITY;
        if (lane < 25) {
            const int n  = lane;
            const int t0 = (256 * n + 49) / 50;     // first a0 contributor
            const int t1 = (256 * n + 255) / 50;    // last  a0 contributor
            float sum = (n > 0) ? pb[t0 - 1] : 0.0f;
            #pragma unroll 6
            for (int t = t0; t <= t1; ++t) sum += pa[t];   // 5-6 iters
            logit = sum;
        }
        float m = logit;
        #pragma unroll
        for (int o = 16; o > 0; o >>= 1)
            m = fmaxf(m, __shfl_xor_sync(0xffffffffu, m, o));
        float e = (lane < 25) ? expf(logit - m) : 0.0f;
        float se = e;
        #pragma unroll
        for (int o = 16; o > 0; o >>= 1)
            se += __shfl_xor_sync(0xffffffffu, se, o);
        const float prb = e / se;        // 0 for lane >= 25

        // offsets: linspace(-3, 2, 5) = -3 + 1.25*k (exact fp32)
        const int ir = lane / 5;
        const int ic = lane - ir * 5;
        float dr = prb * (-3.0f + 1.25f * (float)ir);
        float dc = prb * (-3.0f + 1.25f * (float)ic);
        #pragma unroll
        for (int o = 16; o > 0; o >>= 1) {
            dr += __shfl_xor_sync(0xffffffffu, dr, o);
            dc += __shfl_xor_sync(0xffffffffu, dc, o);
        }
        if (lane == 0) {
            out[2 * pt + 0] = pr + dr;
            out[2 * pt + 1] = pc + dc;
        }
    }
}

extern "C" void kernel_launch(void* const* d_in, const int* in_sizes, int n_in,
                              void* d_out, int out_size)
{
    (void)in_sizes; (void)n_in; (void)out_size;
    // metadata order: 0=source_features (unused by reference), 1=target_features,
    // 2=coarse_positions, 3..6 = Wq,Wk,Wv,Wo (cancel algebraically)
    const float* tf  = (const float*)d_in[1];
    const float* pos = (const float*)d_in[2];
    float* out = (float*)d_out;

    fine_match_kernel<<<B_ * K_, 128>>>(tf, pos, out);
}